// round 2
// baseline (speedup 1.0000x reference)
#include <cuda_runtime.h>
#include <cuda_bf16.h>

#define NN 24576
#define NE 98304
#define NG 512
#define NB 512
#define LL 1000

// ---------------- scratch (device globals; runtime alloc forbidden) ----------------
__device__ float g_h1[NN*128];
__device__ float g_as1[NN*2];
__device__ float g_ad1[NN*2];
__device__ float g_m1[NN*2];
__device__ float g_den1[NN*2];
__device__ float g_out1[NN*128];
__device__ float g_h2[NN*128];
__device__ float g_as2[NN];
__device__ float g_ad2[NN];
__device__ float g_m2[NN];
__device__ float g_den2[NN];
__device__ float g_out2[NN*128];
__device__ float g_sums[NG*128];
__device__ float g_cnt[NG];
__device__ float g_drug[NG*256];
__device__ float g_p1[NB*LL*64];      // conv1 output, [b][l][i]
__device__ float g_pmax[NB*128];
__device__ float g_prot[NB*256];

// ---------------- helpers ----------------
__device__ __forceinline__ unsigned long long ld2(const float* p) {
    return *reinterpret_cast<const unsigned long long*>(p);
}
__device__ __forceinline__ void fma2(unsigned long long& d, unsigned long long a, unsigned long long b) {
    asm("fma.rn.f32x2 %0, %1, %2, %3;" : "=l"(d) : "l"(a), "l"(b), "l"(d));
}
__device__ __forceinline__ float2 up2(unsigned long long v) {
    float2 r; asm("mov.b64 {%0, %1}, %2;" : "=f"(r.x), "=f"(r.y) : "l"(v)); return r;
}
__device__ __forceinline__ void atomicMaxFloat(float* addr, float val) {
    if (val >= 0.f) atomicMax((int*)addr, __float_as_int(val));
    else            atomicMin((unsigned int*)addr, __float_as_uint(val));
}
__device__ __forceinline__ float warp_sum(float v) {
    #pragma unroll
    for (int off = 16; off; off >>= 1) v += __shfl_down_sync(0xffffffffu, v, off);
    return v;
}
__device__ __forceinline__ float elu1(float v) { return v > 0.f ? v : expm1f(v); }

// ---------------- init ----------------
__global__ void k_init() {
    int i = blockIdx.x * blockDim.x + threadIdx.x;
    int stride = gridDim.x * blockDim.x;
    for (int idx = i; idx < NN*128; idx += stride) { g_out1[idx] = 0.f; g_out2[idx] = 0.f; }
    for (int idx = i; idx < NN*2; idx += stride) { g_m1[idx] = -3.0e38f; g_den1[idx] = 0.f; }
    for (int idx = i; idx < NN; idx += stride) { g_m2[idx] = -3.0e38f; g_den2[idx] = 0.f; }
    for (int idx = i; idx < NG*128; idx += stride) g_sums[idx] = 0.f;
    for (int idx = i; idx < NG; idx += stride) g_cnt[idx] = 0.f;
}

// ---------------- GAT1 GEMM: x[N,5] @ W1[5,128] ----------------
__global__ void k_gat1_mm(const float* __restrict__ x, const float* __restrict__ W1) {
    int idx = blockIdx.x * blockDim.x + threadIdx.x;
    if (idx >= NN*128) return;
    int n = idx >> 7, c = idx & 127;
    float acc = 0.f;
    #pragma unroll
    for (int f = 0; f < 5; f++) acc += x[n*5 + f] * W1[f*128 + c];
    g_h1[idx] = acc;
}

// attention scalars, 2 heads of 64
__global__ void k_att1(const float* __restrict__ att_s, const float* __restrict__ att_d) {
    int gw = (blockIdx.x * blockDim.x + threadIdx.x) >> 5;
    int lane = threadIdx.x & 31;
    if (gw >= NN) return;
    const float* hr = g_h1 + (size_t)gw * 128;
    float s0 = hr[lane]*att_s[lane] + hr[lane+32]*att_s[lane+32];
    float s1 = hr[lane+64]*att_s[lane+64] + hr[lane+96]*att_s[lane+96];
    float d0 = hr[lane]*att_d[lane] + hr[lane+32]*att_d[lane+32];
    float d1 = hr[lane+64]*att_d[lane+64] + hr[lane+96]*att_d[lane+96];
    s0 = warp_sum(s0); s1 = warp_sum(s1); d0 = warp_sum(d0); d1 = warp_sum(d1);
    if (lane == 0) {
        g_as1[gw*2] = s0; g_as1[gw*2+1] = s1;
        g_ad1[gw*2] = d0; g_ad1[gw*2+1] = d1;
    }
}

// attention scalars, 1 head of 128
__global__ void k_att2(const float* __restrict__ att_s, const float* __restrict__ att_d) {
    int gw = (blockIdx.x * blockDim.x + threadIdx.x) >> 5;
    int lane = threadIdx.x & 31;
    if (gw >= NN) return;
    const float* hr = g_h2 + (size_t)gw * 128;
    float s = 0.f, d = 0.f;
    #pragma unroll
    for (int t = 0; t < 4; t++) {
        int p = lane + 32*t;
        s += hr[p]*att_s[p];
        d += hr[p]*att_d[p];
    }
    s = warp_sum(s); d = warp_sum(d);
    if (lane == 0) { g_as2[gw] = s; g_ad2[gw] = d; }
}

// ---------------- edge passes (segment softmax + aggregation) ----------------
template<int H>
__global__ void k_edge_max(const int* __restrict__ ei) {
    int e = blockIdx.x * blockDim.x + threadIdx.x;
    const int ET = NE + NN;
    if (e >= ET) return;
    int src, dst;
    if (e < NE) { src = ei[e]; dst = ei[NE + e]; } else { src = dst = e - NE; }
    const float* as_ = (H == 2) ? g_as1 : g_as2;
    const float* ad_ = (H == 2) ? g_ad1 : g_ad2;
    float* m_ = (H == 2) ? g_m1 : g_m2;
    #pragma unroll
    for (int h = 0; h < H; h++) {
        float v = as_[src*H+h] + ad_[dst*H+h];
        v = v > 0.f ? v : 0.2f * v;
        atomicMaxFloat(&m_[dst*H+h], v);
    }
}

template<int H>
__global__ void k_edge_den(const int* __restrict__ ei) {
    int e = blockIdx.x * blockDim.x + threadIdx.x;
    const int ET = NE + NN;
    if (e >= ET) return;
    int src, dst;
    if (e < NE) { src = ei[e]; dst = ei[NE + e]; } else { src = dst = e - NE; }
    const float* as_ = (H == 2) ? g_as1 : g_as2;
    const float* ad_ = (H == 2) ? g_ad1 : g_ad2;
    const float* m_ = (H == 2) ? g_m1 : g_m2;
    float* den_ = (H == 2) ? g_den1 : g_den2;
    #pragma unroll
    for (int h = 0; h < H; h++) {
        float v = as_[src*H+h] + ad_[dst*H+h];
        v = v > 0.f ? v : 0.2f * v;
        atomicAdd(&den_[dst*H+h], expf(v - m_[dst*H+h]));
    }
}

template<int H>
__global__ void k_edge_acc(const int* __restrict__ ei) {
    int gw = (blockIdx.x * blockDim.x + threadIdx.x) >> 5;
    int lane = threadIdx.x & 31;
    const int ET = NE + NN;
    if (gw >= ET) return;
    int src, dst;
    if (gw < NE) { src = ei[gw]; dst = ei[NE + gw]; } else { src = dst = gw - NE; }
    const float* as_ = (H == 2) ? g_as1 : g_as2;
    const float* ad_ = (H == 2) ? g_ad1 : g_ad2;
    const float* m_ = (H == 2) ? g_m1 : g_m2;
    const float* den_ = (H == 2) ? g_den1 : g_den2;
    const float* hin = (H == 2) ? g_h1 : g_h2;
    float* outp = (H == 2) ? g_out1 : g_out2;
    float myalpha = 0.f;
    if (lane < H) {
        int h = lane;
        float v = as_[src*H+h] + ad_[dst*H+h];
        v = v > 0.f ? v : 0.2f * v;
        float w = expf(v - m_[dst*H+h]);
        myalpha = w / (den_[dst*H+h] + 1e-16f);
    }
    float a0 = __shfl_sync(0xffffffffu, myalpha, 0);
    float a1 = (H == 2) ? __shfl_sync(0xffffffffu, myalpha, 1) : a0;
    const float* hr = hin + (size_t)src * 128;
    float* orow = outp + (size_t)dst * 128;
    #pragma unroll
    for (int t = 0; t < 4; t++) {
        int p = lane + 32*t;
        float a = (H == 2 && p >= 64) ? a1 : a0;
        atomicAdd(&orow[p], hr[p] * a);
    }
}

template<int WHICH>
__global__ void k_bias_elu(const float* __restrict__ b) {
    int idx = blockIdx.x * blockDim.x + threadIdx.x;
    if (idx >= NN*128) return;
    float* o = (WHICH == 1) ? g_out1 : g_out2;
    o[idx] = elu1(o[idx] + b[idx & 127]);
}

// ---------------- GAT2 GEMM: out1[N,128] @ W2[128,128] -> g_h2 ----------------
__global__ void __launch_bounds__(256) k_gat2_mm(const float* __restrict__ W2) {
    extern __shared__ float sm[];
    float* sg = sm;            // 64 x 128
    float* sw = sm + 64*128;   // 128 x 128
    int base = blockIdx.x * 64;
    int tid = threadIdx.x;
    for (int idx = tid; idx < 64*128; idx += 256) sg[idx] = g_out1[(size_t)base*128 + idx];
    for (int idx = tid; idx < 128*128; idx += 256) sw[idx] = W2[idx];
    __syncthreads();
    int r0 = (tid >> 4) << 2;
    int c0 = (tid & 15) << 3;
    float acc[4][8];
    #pragma unroll
    for (int i = 0; i < 4; i++)
        #pragma unroll
        for (int j = 0; j < 8; j++) acc[i][j] = 0.f;
    #pragma unroll 4
    for (int k = 0; k < 128; k++) {
        float a[4];
        #pragma unroll
        for (int i = 0; i < 4; i++) a[i] = sg[(r0+i)*128 + k];
        float4 b0 = *reinterpret_cast<const float4*>(&sw[k*128 + c0]);
        float4 b1 = *reinterpret_cast<const float4*>(&sw[k*128 + c0 + 4]);
        #pragma unroll
        for (int i = 0; i < 4; i++) {
            acc[i][0] += a[i]*b0.x; acc[i][1] += a[i]*b0.y;
            acc[i][2] += a[i]*b0.z; acc[i][3] += a[i]*b0.w;
            acc[i][4] += a[i]*b1.x; acc[i][5] += a[i]*b1.y;
            acc[i][6] += a[i]*b1.z; acc[i][7] += a[i]*b1.w;
        }
    }
    #pragma unroll
    for (int i = 0; i < 4; i++) {
        float4 v0 = make_float4(acc[i][0], acc[i][1], acc[i][2], acc[i][3]);
        float4 v1 = make_float4(acc[i][4], acc[i][5], acc[i][6], acc[i][7]);
        *reinterpret_cast<float4*>(&g_h2[(size_t)(base+r0+i)*128 + c0]) = v0;
        *reinterpret_cast<float4*>(&g_h2[(size_t)(base+r0+i)*128 + c0 + 4]) = v1;
    }
}

// ---------------- mean pooling + drug dense ----------------
__global__ void k_pool(const int* __restrict__ batch) {
    int gw = (blockIdx.x * blockDim.x + threadIdx.x) >> 5;
    int lane = threadIdx.x & 31;
    if (gw >= NN) return;
    int g = batch[gw];
    const float* r = g_out2 + (size_t)gw * 128;
    #pragma unroll
    for (int t = 0; t < 4; t++) {
        int p = lane + 32*t;
        atomicAdd(&g_sums[g*128 + p], r[p]);
    }
    if (lane == 0) atomicAdd(&g_cnt[g], 1.0f);
}

__global__ void k_drug(const float* __restrict__ Wd, const float* __restrict__ bd) {
    int idx = blockIdx.x * blockDim.x + threadIdx.x;
    if (idx >= NG*256) return;
    int g = idx >> 8, j = idx & 255;
    float invc = 1.f / fmaxf(g_cnt[g], 1.f);
    const float* srow = g_sums + g*128;
    float acc = 0.f;
    #pragma unroll 4
    for (int k = 0; k < 128; k++) acc += srow[k] * Wd[k*256 + j];
    g_drug[idx] = fmaxf(acc * invc + bd[j], 0.f);
}

// ---------------- conv1 (fused embedding gather), block per batch ----------------
// out[b,o,l] = elu( sum_{i,k} Pe[seq[b,l+k-1], i] * K1[o,i,k] + bk1[o] ), stored [b][l][o]
__global__ void __launch_bounds__(256) k_conv1(const int* __restrict__ seq, const float* __restrict__ Pe,
                                               const float* __restrict__ K1, const float* __restrict__ bk1) {
    extern __shared__ float sm[];
    float* sk = sm;            // 64 o x 194  ([o][k*64+i])
    float* sp = sm + 64*194;   // 66 rows x 66
    int b = blockIdx.x, tid = threadIdx.x;
    for (int idx = tid; idx < 64*192; idx += 256) {
        int o = idx / 192, r = idx - o*192;
        int k = r >> 6, i = r & 63;
        sk[o*194 + k*64 + i] = K1[(o*64 + i)*3 + k];
    }
    int o0 = 4*(tid >> 4), lgrp = tid & 15;
    float bloc[4];
    #pragma unroll
    for (int a = 0; a < 4; a++) bloc[a] = bk1[o0 + a];
    for (int t = 0; t < 16; t++) {
        int l0 = t*64;
        __syncthreads();
        for (int idx = tid; idx < 66*64; idx += 256) {
            int row = idx >> 6, i = idx & 63;
            int lg = l0 - 1 + row;
            sp[row*66 + i] = (lg >= 0 && lg < LL) ? Pe[seq[b*LL + lg]*64 + i] : 0.f;
        }
        __syncthreads();
        unsigned long long acc[4][4];
        #pragma unroll
        for (int a = 0; a < 4; a++)
            #pragma unroll
            for (int j = 0; j < 4; j++) acc[a][j] = 0ull;
        #pragma unroll 2
        for (int ib = 0; ib < 64; ib += 2) {
            #pragma unroll
            for (int k = 0; k < 3; k++) {
                unsigned long long kk[4], pp[4];
                #pragma unroll
                for (int a = 0; a < 4; a++) kk[a] = ld2(sk + (o0+a)*194 + k*64 + ib);
                #pragma unroll
                for (int j = 0; j < 4; j++) pp[j] = ld2(sp + (lgrp + 16*j + k)*66 + ib);
                #pragma unroll
                for (int a = 0; a < 4; a++)
                    #pragma unroll
                    for (int j = 0; j < 4; j++) fma2(acc[a][j], pp[j], kk[a]);
            }
        }
        #pragma unroll
        for (int j = 0; j < 4; j++) {
            int l = l0 + lgrp + 16*j;
            if (l < LL) {
                float4 v;
                float* pv = reinterpret_cast<float*>(&v);
                #pragma unroll
                for (int a = 0; a < 4; a++) {
                    float2 f = up2(acc[a][j]);
                    pv[a] = elu1(f.x + f.y + bloc[a]);
                }
                *reinterpret_cast<float4*>(&g_p1[((size_t)b*LL + l)*64 + o0]) = v;
            }
        }
    }
}

// ---------------- conv2 + fused global max pool, block per batch ----------------
__global__ void __launch_bounds__(256) k_conv2(const float* __restrict__ K2, const float* __restrict__ bk2) {
    extern __shared__ float sm[];
    float* sk = sm;              // 128 o x 322 ([o][k*64+i])
    float* sp = sm + 128*322;    // 68 rows x 66
    int b = blockIdx.x, tid = threadIdx.x;
    for (int idx = tid; idx < 128*320; idx += 256) {
        int o = idx / 320, r = idx - o*320;
        int k = r >> 6, i = r & 63;
        sk[o*322 + k*64 + i] = K2[(o*64 + i)*5 + k];
    }
    int o0 = 8*(tid >> 4), lgrp = tid & 15;
    float bloc[8], rmax[8];
    #pragma unroll
    for (int a = 0; a < 8; a++) { bloc[a] = bk2[o0 + a]; rmax[a] = -3.0e38f; }
    for (int t = 0; t < 16; t++) {
        int l0 = t*64;
        __syncthreads();
        for (int idx = tid; idx < 68*64; idx += 256) {
            int row = idx >> 6, i = idx & 63;
            int lg = l0 - 2 + row;
            sp[row*66 + i] = (lg >= 0 && lg < LL) ? g_p1[((size_t)b*LL + lg)*64 + i] : 0.f;
        }
        __syncthreads();
        unsigned long long acc[8][4];
        #pragma unroll
        for (int a = 0; a < 8; a++)
            #pragma unroll
            for (int j = 0; j < 4; j++) acc[a][j] = 0ull;
        #pragma unroll 1
        for (int ib = 0; ib < 64; ib += 2) {
            #pragma unroll
            for (int k = 0; k < 5; k++) {
                unsigned long long kk[8], pp[4];
                #pragma unroll
                for (int a = 0; a < 8; a++) kk[a] = ld2(sk + (o0+a)*322 + k*64 + ib);
                #pragma unroll
                for (int j = 0; j < 4; j++) pp[j] = ld2(sp + (lgrp + 16*j + k)*66 + ib);
                #pragma unroll
                for (int a = 0; a < 8; a++)
                    #pragma unroll
                    for (int j = 0; j < 4; j++) fma2(acc[a][j], pp[j], kk[a]);
            }
        }
        #pragma unroll
        for (int j = 0; j < 4; j++) {
            int l = l0 + lgrp + 16*j;
            if (l < LL) {
                #pragma unroll
                for (int a = 0; a < 8; a++) {
                    float2 f = up2(acc[a][j]);
                    rmax[a] = fmaxf(rmax[a], elu1(f.x + f.y + bloc[a]));
                }
            }
        }
    }
    // reduce max over the 16 l-groups (reuse sp region: 128 x 16)
    __syncthreads();
    #pragma unroll
    for (int a = 0; a < 8; a++) sp[(o0+a)*16 + lgrp] = rmax[a];
    __syncthreads();
    if (tid < 128) {
        float m = -3.0e38f;
        #pragma unroll
        for (int q = 0; q < 16; q++) m = fmaxf(m, sp[tid*16 + q]);
        g_pmax[b*128 + tid] = m;
    }
}

__global__ void k_prot(const float* __restrict__ Wp, const float* __restrict__ bp) {
    int idx = blockIdx.x * blockDim.x + threadIdx.x;
    if (idx >= NB*256) return;
    int g = idx >> 8, j = idx & 255;
    const float* srow = g_pmax + g*128;
    float acc = 0.f;
    #pragma unroll 4
    for (int k = 0; k < 128; k++) acc += srow[k] * Wp[k*256 + j];
    g_prot[idx] = fmaxf(acc + bp[j], 0.f);
}

// ---------------- head MLP: [drug|prot] @ Wf1 -> Wf2 -> Wo ----------------
__global__ void __launch_bounds__(128) k_head(const float* __restrict__ Wf1, const float* __restrict__ bf1,
                                              const float* __restrict__ Wf2, const float* __restrict__ bf2,
                                              const float* __restrict__ Wo, const float* __restrict__ bo,
                                              float* __restrict__ out) {
    __shared__ float sh[512];
    __shared__ float s1[128];
    __shared__ float s2[64];
    int g = blockIdx.x, tid = threadIdx.x;
    for (int i = tid; i < 256; i += 128) {
        sh[i]       = g_drug[g*256 + i];
        sh[256 + i] = g_prot[g*256 + i];
    }
    __syncthreads();
    float acc = 0.f;
    #pragma unroll 8
    for (int k = 0; k < 512; k++) acc += sh[k] * Wf1[k*128 + tid];
    s1[tid] = fmaxf(acc + bf1[tid], 0.f);
    __syncthreads();
    if (tid < 64) {
        float a = 0.f;
        #pragma unroll 8
        for (int k = 0; k < 128; k++) a += s1[k] * Wf2[k*64 + tid];
        s2[tid] = fmaxf(a + bf2[tid], 0.f);
    }
    __syncthreads();
    if (tid < 32) {
        float a = s2[tid]*Wo[tid] + s2[tid+32]*Wo[tid+32];
        a = warp_sum(a);
        if (tid == 0) out[g] = a + bo[0];
    }
}

// ---------------- launch ----------------
extern "C" void kernel_launch(void* const* d_in, const int* in_sizes, int n_in,
                              void* d_out, int out_size) {
    const float* x        = (const float*)d_in[0];
    const int*   ei       = (const int*)d_in[1];
    const int*   batch    = (const int*)d_in[2];
    const int*   seq      = (const int*)d_in[3];
    const float* W1       = (const float*)d_in[4];
    const float* att_s1   = (const float*)d_in[5];
    const float* att_d1   = (const float*)d_in[6];
    const float* b1       = (const float*)d_in[7];
    const float* W2       = (const float*)d_in[8];
    const float* att_s2   = (const float*)d_in[9];
    const float* att_d2   = (const float*)d_in[10];
    const float* b2       = (const float*)d_in[11];
    const float* Wd       = (const float*)d_in[12];
    const float* bd       = (const float*)d_in[13];
    const float* Pe       = (const float*)d_in[14];
    const float* K1       = (const float*)d_in[15];
    const float* bk1      = (const float*)d_in[16];
    const float* K2       = (const float*)d_in[17];
    const float* bk2      = (const float*)d_in[18];
    const float* Wp       = (const float*)d_in[19];
    const float* bp       = (const float*)d_in[20];
    const float* Wf1      = (const float*)d_in[21];
    const float* bf1      = (const float*)d_in[22];
    const float* Wf2      = (const float*)d_in[23];
    const float* bf2      = (const float*)d_in[24];
    const float* Wo       = (const float*)d_in[25];
    const float* bo       = (const float*)d_in[26];
    float* out = (float*)d_out;

    cudaFuncSetAttribute(k_gat2_mm, cudaFuncAttributeMaxDynamicSharedMemorySize, 98304);
    cudaFuncSetAttribute(k_conv1,   cudaFuncAttributeMaxDynamicSharedMemorySize, 67088);
    cudaFuncSetAttribute(k_conv2,   cudaFuncAttributeMaxDynamicSharedMemorySize, 182816);

    const int ET = NE + NN;

    k_init<<<2048, 256>>>();

    // protein branch (independent; schedule convs early)
    k_conv1<<<NB, 256, 67088>>>(seq, Pe, K1, bk1);
    k_conv2<<<NB, 256, 182816>>>(K2, bk2);
    k_prot<<<(NB*256 + 255)/256, 256>>>(Wp, bp);

    // drug branch: GAT layer 1
    k_gat1_mm<<<(NN*128 + 255)/256, 256>>>(x, W1);
    k_att1<<<(NN*32 + 255)/256, 256>>>(att_s1, att_d1);
    k_edge_max<2><<<(ET + 255)/256, 256>>>(ei);
    k_edge_den<2><<<(ET + 255)/256, 256>>>(ei);
    k_edge_acc<2><<<(ET*32 + 255)/256, 256>>>(ei);
    k_bias_elu<1><<<(NN*128 + 255)/256, 256>>>(b1);

    // GAT layer 2
    k_gat2_mm<<<NN/64, 256, 98304>>>(W2);
    k_att2<<<(NN*32 + 255)/256, 256>>>(att_s2, att_d2);
    k_edge_max<1><<<(ET + 255)/256, 256>>>(ei);
    k_edge_den<1><<<(ET + 255)/256, 256>>>(ei);
    k_edge_acc<1><<<(ET*32 + 255)/256, 256>>>(ei);
    k_bias_elu<2><<<(NN*128 + 255)/256, 256>>>(b2);

    // pooling + drug dense
    k_pool<<<(NN*32 + 255)/256, 256>>>(batch);
    k_drug<<<(NG*256 + 255)/256, 256>>>(Wd, bd);

    // head
    k_head<<<NG, 128>>>(Wf1, bf1, Wf2, bf2, Wo, bo, out);
}

// round 3
// speedup vs baseline: 1.3955x; 1.3955x over previous
#include <cuda_runtime.h>
#include <cuda_bf16.h>

#define NN 24576
#define NE 98304
#define NG 512
#define NB 512
#define LL 1000

// ---------------- scratch (device globals; runtime alloc forbidden) ----------------
__device__ float g_h1[NN*128];
__device__ float g_as1[NN*2];
__device__ float g_ad1[NN*2];
__device__ float g_m1[NN*2];
__device__ float g_den1[NN*2];
__device__ float g_e1[(NE+NN)*2];
__device__ float g_out1[NN*128];
__device__ float g_h2[NN*128];
__device__ float g_as2[NN];
__device__ float g_ad2[NN];
__device__ float g_m2[NN];
__device__ float g_den2[NN];
__device__ float g_e2[NE+NN];
__device__ float g_out2[NN*128];
__device__ float g_sums[NG*128];
__device__ float g_cnt[NG];
__device__ float g_drug[NG*256];
__device__ float g_T[3*22*64];        // conv1 token tables (bias folded into k=1)
__device__ float g_p1[NB*LL*64];      // conv1 output, [b][l][i]
__device__ float g_pmax[NB*128];
__device__ float g_prot[NB*256];

// ---------------- helpers ----------------
__device__ __forceinline__ unsigned long long ld2(const float* p) {
    return *reinterpret_cast<const unsigned long long*>(p);
}
__device__ __forceinline__ void fma2(unsigned long long& d, unsigned long long a, unsigned long long b) {
    asm("fma.rn.f32x2 %0, %1, %2, %3;" : "=l"(d) : "l"(a), "l"(b), "l"(d));
}
__device__ __forceinline__ float2 up2(unsigned long long v) {
    float2 r; asm("mov.b64 {%0, %1}, %2;" : "=f"(r.x), "=f"(r.y) : "l"(v)); return r;
}
__device__ __forceinline__ void red_add_v4(float* addr, float4 v) {
    asm volatile("red.global.add.v4.f32 [%0], {%1, %2, %3, %4};"
                 :: "l"(addr), "f"(v.x), "f"(v.y), "f"(v.z), "f"(v.w) : "memory");
}
__device__ __forceinline__ void atomicMaxFloat(float* addr, float val) {
    if (val >= 0.f) atomicMax((int*)addr, __float_as_int(val));
    else            atomicMin((unsigned int*)addr, __float_as_uint(val));
}
__device__ __forceinline__ float warp_sum(float v) {
    #pragma unroll
    for (int off = 16; off; off >>= 1) v += __shfl_down_sync(0xffffffffu, v, off);
    return v;
}
__device__ __forceinline__ float elu1(float v) { return v > 0.f ? v : expm1f(v); }

// ---------------- conv1 token tables: T[k][t][o] = sum_i Pe[t,i] * K1[o,i,k] ----------------
__global__ void k_tab(const float* __restrict__ Pe, const float* __restrict__ K1,
                      const float* __restrict__ bk1) {
    int idx = blockIdx.x * blockDim.x + threadIdx.x;
    if (idx >= 3*22*64) return;
    int o = idx & 63, r = idx >> 6;
    int t = r % 22, k = r / 22;
    float acc = (k == 1) ? bk1[o] : 0.f;
    #pragma unroll 8
    for (int i = 0; i < 64; i++) acc += Pe[t*64 + i] * K1[(o*64 + i)*3 + k];
    g_T[idx] = acc;
}

// ---------------- conv1 apply: gather + add + elu, writes g_p1 [b][l][64] ----------------
__global__ void __launch_bounds__(256) k_conv1_apply(const int* __restrict__ seq) {
    int b = blockIdx.y;
    int lofs = threadIdx.x >> 4, lq = threadIdx.x & 15;
    int l = blockIdx.x * 16 + lofs;
    if (l >= LL) return;
    int s1 = seq[b*LL + l];
    int c = lq * 4;
    float4 v = *reinterpret_cast<const float4*>(&g_T[(22 + s1)*64 + c]);
    if (l > 0) {
        int s0 = seq[b*LL + l - 1];
        float4 a = *reinterpret_cast<const float4*>(&g_T[s0*64 + c]);
        v.x += a.x; v.y += a.y; v.z += a.z; v.w += a.w;
    }
    if (l < LL-1) {
        int s2 = seq[b*LL + l + 1];
        float4 a = *reinterpret_cast<const float4*>(&g_T[(44 + s2)*64 + c]);
        v.x += a.x; v.y += a.y; v.z += a.z; v.w += a.w;
    }
    v.x = elu1(v.x); v.y = elu1(v.y); v.z = elu1(v.z); v.w = elu1(v.w);
    *reinterpret_cast<float4*>(&g_p1[((size_t)b*LL + l)*64 + c]) = v;
}

// ---------------- init ----------------
__global__ void k_init() {
    int i = blockIdx.x * blockDim.x + threadIdx.x;
    int stride = gridDim.x * blockDim.x;
    for (int idx = i; idx < NN*128; idx += stride) { g_out1[idx] = 0.f; g_out2[idx] = 0.f; }
    for (int idx = i; idx < NN*2; idx += stride) { g_m1[idx] = -3.0e38f; g_den1[idx] = 0.f; }
    for (int idx = i; idx < NN; idx += stride) { g_m2[idx] = -3.0e38f; g_den2[idx] = 0.f; }
    for (int idx = i; idx < NG*128; idx += stride) g_sums[idx] = 0.f;
    for (int idx = i; idx < NG; idx += stride) g_cnt[idx] = 0.f;
    for (int idx = i; idx < NB*128; idx += stride) g_pmax[idx] = -3.0e38f;
}

// ---------------- conv2 + fused global max pool, persistent over tiles ----------------
__global__ void __launch_bounds__(256) k_conv2(const float* __restrict__ K2, const float* __restrict__ bk2) {
    extern __shared__ float sm[];
    float* sk = sm;              // 128 o x 322 ([o][k*64+i])
    float* sp = sm + 128*322;    // 68 rows x 66
    int tid = threadIdx.x;
    for (int idx = tid; idx < 128*320; idx += 256) {
        int o = idx / 320, r = idx - o*320;
        int k = r >> 6, i = r & 63;
        sk[o*322 + k*64 + i] = K2[(o*64 + i)*5 + k];
    }
    int o0 = 8*(tid >> 4), lgrp = tid & 15;
    float bloc[8];
    #pragma unroll
    for (int a = 0; a < 8; a++) bloc[a] = bk2[o0 + a];

    for (int tile = blockIdx.x; tile < NB*16; tile += gridDim.x) {
        int b = tile >> 4, l0 = (tile & 15) * 64;
        __syncthreads();
        for (int idx = tid; idx < 68*64; idx += 256) {
            int row = idx >> 6, i = idx & 63;
            int lg = l0 - 2 + row;
            sp[row*66 + i] = (lg >= 0 && lg < LL) ? g_p1[((size_t)b*LL + lg)*64 + i] : 0.f;
        }
        __syncthreads();
        unsigned long long acc[8][4];
        #pragma unroll
        for (int a = 0; a < 8; a++)
            #pragma unroll
            for (int j = 0; j < 4; j++) acc[a][j] = 0ull;
        #pragma unroll 1
        for (int ib = 0; ib < 64; ib += 2) {
            #pragma unroll
            for (int k = 0; k < 5; k++) {
                unsigned long long kk[8], pp[4];
                #pragma unroll
                for (int a = 0; a < 8; a++) kk[a] = ld2(sk + (o0+a)*322 + k*64 + ib);
                #pragma unroll
                for (int j = 0; j < 4; j++) pp[j] = ld2(sp + (lgrp + 16*j + k)*66 + ib);
                #pragma unroll
                for (int a = 0; a < 8; a++)
                    #pragma unroll
                    for (int j = 0; j < 4; j++) fma2(acc[a][j], pp[j], kk[a]);
            }
        }
        float rmax[8];
        #pragma unroll
        for (int a = 0; a < 8; a++) rmax[a] = -3.0e38f;
        #pragma unroll
        for (int j = 0; j < 4; j++) {
            int l = l0 + lgrp + 16*j;
            if (l < LL) {
                #pragma unroll
                for (int a = 0; a < 8; a++) {
                    float2 f = up2(acc[a][j]);
                    rmax[a] = fmaxf(rmax[a], elu1(f.x + f.y + bloc[a]));
                }
            }
        }
        __syncthreads();   // all compute reads of sp done before reuse as reduce buffer
        #pragma unroll
        for (int a = 0; a < 8; a++) sp[(o0+a)*16 + lgrp] = rmax[a];
        __syncthreads();
        if (tid < 128) {
            float m = -3.0e38f;
            #pragma unroll
            for (int q = 0; q < 16; q++) m = fmaxf(m, sp[tid*16 + q]);
            atomicMaxFloat(&g_pmax[b*128 + tid], m);
        }
        // loop-top __syncthreads protects sp before next fill
    }
}

// ---------------- GAT1 GEMM: x[N,5] @ W1[5,128] ----------------
__global__ void k_gat1_mm(const float* __restrict__ x, const float* __restrict__ W1) {
    int idx = blockIdx.x * blockDim.x + threadIdx.x;
    if (idx >= NN*128) return;
    int n = idx >> 7, c = idx & 127;
    float acc = 0.f;
    #pragma unroll
    for (int f = 0; f < 5; f++) acc += x[n*5 + f] * W1[f*128 + c];
    g_h1[idx] = acc;
}

// attention scalars, 2 heads of 64
__global__ void k_att1(const float* __restrict__ att_s, const float* __restrict__ att_d) {
    int gw = (blockIdx.x * blockDim.x + threadIdx.x) >> 5;
    int lane = threadIdx.x & 31;
    if (gw >= NN) return;
    const float* hr = g_h1 + (size_t)gw * 128;
    float s0 = hr[lane]*att_s[lane] + hr[lane+32]*att_s[lane+32];
    float s1 = hr[lane+64]*att_s[lane+64] + hr[lane+96]*att_s[lane+96];
    float d0 = hr[lane]*att_d[lane] + hr[lane+32]*att_d[lane+32];
    float d1 = hr[lane+64]*att_d[lane+64] + hr[lane+96]*att_d[lane+96];
    s0 = warp_sum(s0); s1 = warp_sum(s1); d0 = warp_sum(d0); d1 = warp_sum(d1);
    if (lane == 0) {
        g_as1[gw*2] = s0; g_as1[gw*2+1] = s1;
        g_ad1[gw*2] = d0; g_ad1[gw*2+1] = d1;
    }
}

// attention scalars, 1 head of 128
__global__ void k_att2(const float* __restrict__ att_s, const float* __restrict__ att_d) {
    int gw = (blockIdx.x * blockDim.x + threadIdx.x) >> 5;
    int lane = threadIdx.x & 31;
    if (gw >= NN) return;
    const float* hr = g_h2 + (size_t)gw * 128;
    float s = 0.f, d = 0.f;
    #pragma unroll
    for (int t = 0; t < 4; t++) {
        int p = lane + 32*t;
        s += hr[p]*att_s[p];
        d += hr[p]*att_d[p];
    }
    s = warp_sum(s); d = warp_sum(d);
    if (lane == 0) { g_as2[gw] = s; g_ad2[gw] = d; }
}

// ---------------- edge passes (segment softmax + aggregation) ----------------
template<int H>
__global__ void k_edge_max(const int* __restrict__ ei) {
    int e = blockIdx.x * blockDim.x + threadIdx.x;
    const int ET = NE + NN;
    if (e >= ET) return;
    int src, dst;
    if (e < NE) { src = ei[e]; dst = ei[NE + e]; } else { src = dst = e - NE; }
    const float* as_ = (H == 2) ? g_as1 : g_as2;
    const float* ad_ = (H == 2) ? g_ad1 : g_ad2;
    float* m_ = (H == 2) ? g_m1 : g_m2;
    float* e_ = (H == 2) ? g_e1 : g_e2;
    #pragma unroll
    for (int h = 0; h < H; h++) {
        float v = as_[src*H+h] + ad_[dst*H+h];
        v = v > 0.f ? v : 0.2f * v;
        e_[e*H+h] = v;
        atomicMaxFloat(&m_[dst*H+h], v);
    }
}

template<int H>
__global__ void k_edge_den(const int* __restrict__ ei) {
    int e = blockIdx.x * blockDim.x + threadIdx.x;
    const int ET = NE + NN;
    if (e >= ET) return;
    int dst = (e < NE) ? ei[NE + e] : (e - NE);
    const float* m_ = (H == 2) ? g_m1 : g_m2;
    float* den_ = (H == 2) ? g_den1 : g_den2;
    float* e_ = (H == 2) ? g_e1 : g_e2;
    #pragma unroll
    for (int h = 0; h < H; h++) {
        float w = expf(e_[e*H+h] - m_[dst*H+h]);
        e_[e*H+h] = w;                       // cache weight for the acc pass
        atomicAdd(&den_[dst*H+h], w);
    }
}

template<int H>
__global__ void k_edge_acc(const int* __restrict__ ei) {
    int gw = (blockIdx.x * blockDim.x + threadIdx.x) >> 5;
    int lane = threadIdx.x & 31;
    const int ET = NE + NN;
    if (gw >= ET) return;
    int src, dst;
    if (gw < NE) { src = ei[gw]; dst = ei[NE + gw]; } else { src = dst = gw - NE; }
    const float* den_ = (H == 2) ? g_den1 : g_den2;
    const float* e_ = (H == 2) ? g_e1 : g_e2;
    const float* hin = (H == 2) ? g_h1 : g_h2;
    float* outp = (H == 2) ? g_out1 : g_out2;
    int h = (H == 2 && lane >= 16) ? 1 : 0;
    float alpha = e_[gw*H + h] / (den_[dst*H + h] + 1e-16f);
    float4 v = *reinterpret_cast<const float4*>(&hin[(size_t)src*128 + lane*4]);
    v.x *= alpha; v.y *= alpha; v.z *= alpha; v.w *= alpha;
    red_add_v4(&outp[(size_t)dst*128 + lane*4], v);
}

template<int WHICH>
__global__ void k_bias_elu(const float* __restrict__ b) {
    int idx = blockIdx.x * blockDim.x + threadIdx.x;
    if (idx >= NN*128) return;
    float* o = (WHICH == 1) ? g_out1 : g_out2;
    o[idx] = elu1(o[idx] + b[idx & 127]);
}

// ---------------- GAT2 GEMM: out1[N,128] @ W2[128,128] -> g_h2 ----------------
__global__ void __launch_bounds__(256) k_gat2_mm(const float* __restrict__ W2) {
    extern __shared__ float sm[];
    float* sg = sm;            // 64 x 128
    float* sw = sm + 64*128;   // 128 x 128
    int base = blockIdx.x * 64;
    int tid = threadIdx.x;
    for (int idx = tid; idx < 64*128; idx += 256) sg[idx] = g_out1[(size_t)base*128 + idx];
    for (int idx = tid; idx < 128*128; idx += 256) sw[idx] = W2[idx];
    __syncthreads();
    int r0 = (tid >> 4) << 2;
    int c0 = (tid & 15) << 3;
    float acc[4][8];
    #pragma unroll
    for (int i = 0; i < 4; i++)
        #pragma unroll
        for (int j = 0; j < 8; j++) acc[i][j] = 0.f;
    #pragma unroll 4
    for (int k = 0; k < 128; k++) {
        float a[4];
        #pragma unroll
        for (int i = 0; i < 4; i++) a[i] = sg[(r0+i)*128 + k];
        float4 b0 = *reinterpret_cast<const float4*>(&sw[k*128 + c0]);
        float4 b1 = *reinterpret_cast<const float4*>(&sw[k*128 + c0 + 4]);
        #pragma unroll
        for (int i = 0; i < 4; i++) {
            acc[i][0] += a[i]*b0.x; acc[i][1] += a[i]*b0.y;
            acc[i][2] += a[i]*b0.z; acc[i][3] += a[i]*b0.w;
            acc[i][4] += a[i]*b1.x; acc[i][5] += a[i]*b1.y;
            acc[i][6] += a[i]*b1.z; acc[i][7] += a[i]*b1.w;
        }
    }
    #pragma unroll
    for (int i = 0; i < 4; i++) {
        float4 v0 = make_float4(acc[i][0], acc[i][1], acc[i][2], acc[i][3]);
        float4 v1 = make_float4(acc[i][4], acc[i][5], acc[i][6], acc[i][7]);
        *reinterpret_cast<float4*>(&g_h2[(size_t)(base+r0+i)*128 + c0]) = v0;
        *reinterpret_cast<float4*>(&g_h2[(size_t)(base+r0+i)*128 + c0 + 4]) = v1;
    }
}

// ---------------- mean pooling + drug dense ----------------
__global__ void k_pool(const int* __restrict__ batch) {
    int gw = (blockIdx.x * blockDim.x + threadIdx.x) >> 5;
    int lane = threadIdx.x & 31;
    if (gw >= NN) return;
    int g = batch[gw];
    float4 v = *reinterpret_cast<const float4*>(&g_out2[(size_t)gw*128 + lane*4]);
    red_add_v4(&g_sums[g*128 + lane*4], v);
    if (lane == 0) atomicAdd(&g_cnt[g], 1.0f);
}

__global__ void k_drug(const float* __restrict__ Wd, const float* __restrict__ bd) {
    int idx = blockIdx.x * blockDim.x + threadIdx.x;
    if (idx >= NG*256) return;
    int g = idx >> 8, j = idx & 255;
    float invc = 1.f / fmaxf(g_cnt[g], 1.f);
    const float* srow = g_sums + g*128;
    float acc = 0.f;
    #pragma unroll 4
    for (int k = 0; k < 128; k++) acc += srow[k] * Wd[k*256 + j];
    g_drug[idx] = fmaxf(acc * invc + bd[j], 0.f);
}

__global__ void k_prot(const float* __restrict__ Wp, const float* __restrict__ bp) {
    int idx = blockIdx.x * blockDim.x + threadIdx.x;
    if (idx >= NB*256) return;
    int g = idx >> 8, j = idx & 255;
    const float* srow = g_pmax + g*128;
    float acc = 0.f;
    #pragma unroll 4
    for (int k = 0; k < 128; k++) acc += srow[k] * Wp[k*256 + j];
    g_prot[idx] = fmaxf(acc + bp[j], 0.f);
}

// ---------------- head MLP: [drug|prot] @ Wf1 -> Wf2 -> Wo ----------------
__global__ void __launch_bounds__(128) k_head(const float* __restrict__ Wf1, const float* __restrict__ bf1,
                                              const float* __restrict__ Wf2, const float* __restrict__ bf2,
                                              const float* __restrict__ Wo, const float* __restrict__ bo,
                                              float* __restrict__ out) {
    __shared__ float sh[512];
    __shared__ float s1[128];
    __shared__ float s2[64];
    int g = blockIdx.x, tid = threadIdx.x;
    for (int i = tid; i < 256; i += 128) {
        sh[i]       = g_drug[g*256 + i];
        sh[256 + i] = g_prot[g*256 + i];
    }
    __syncthreads();
    float acc = 0.f;
    #pragma unroll 8
    for (int k = 0; k < 512; k++) acc += sh[k] * Wf1[k*128 + tid];
    s1[tid] = fmaxf(acc + bf1[tid], 0.f);
    __syncthreads();
    if (tid < 64) {
        float a = 0.f;
        #pragma unroll 8
        for (int k = 0; k < 128; k++) a += s1[k] * Wf2[k*64 + tid];
        s2[tid] = fmaxf(a + bf2[tid], 0.f);
    }
    __syncthreads();
    if (tid < 32) {
        float a = s2[tid]*Wo[tid] + s2[tid+32]*Wo[tid+32];
        a = warp_sum(a);
        if (tid == 0) out[g] = a + bo[0];
    }
}

// ---------------- launch ----------------
extern "C" void kernel_launch(void* const* d_in, const int* in_sizes, int n_in,
                              void* d_out, int out_size) {
    const float* x        = (const float*)d_in[0];
    const int*   ei       = (const int*)d_in[1];
    const int*   batch    = (const int*)d_in[2];
    const int*   seq      = (const int*)d_in[3];
    const float* W1       = (const float*)d_in[4];
    const float* att_s1   = (const float*)d_in[5];
    const float* att_d1   = (const float*)d_in[6];
    const float* b1       = (const float*)d_in[7];
    const float* W2       = (const float*)d_in[8];
    const float* att_s2   = (const float*)d_in[9];
    const float* att_d2   = (const float*)d_in[10];
    const float* b2       = (const float*)d_in[11];
    const float* Wd       = (const float*)d_in[12];
    const float* bd       = (const float*)d_in[13];
    const float* Pe       = (const float*)d_in[14];
    const float* K1       = (const float*)d_in[15];
    const float* bk1      = (const float*)d_in[16];
    const float* K2       = (const float*)d_in[17];
    const float* bk2      = (const float*)d_in[18];
    const float* Wp       = (const float*)d_in[19];
    const float* bp       = (const float*)d_in[20];
    const float* Wf1      = (const float*)d_in[21];
    const float* bf1      = (const float*)d_in[22];
    const float* Wf2      = (const float*)d_in[23];
    const float* bf2      = (const float*)d_in[24];
    const float* Wo       = (const float*)d_in[25];
    const float* bo       = (const float*)d_in[26];
    float* out = (float*)d_out;

    cudaFuncSetAttribute(k_gat2_mm, cudaFuncAttributeMaxDynamicSharedMemorySize, 98304);
    cudaFuncSetAttribute(k_conv2,   cudaFuncAttributeMaxDynamicSharedMemorySize, 182816);

    const int ET = NE + NN;

    // protein branch
    k_tab<<<17, 256>>>(Pe, K1, bk1);                               // 0
    {
        dim3 grid((LL + 15)/16, NB);
        k_conv1_apply<<<grid, 256>>>(seq);                         // 1
    }
    k_init<<<2048, 256>>>();                                       // 2
    k_conv2<<<148, 256, 182816>>>(K2, bk2);                        // 3  <- profile target
    k_prot<<<(NB*256 + 255)/256, 256>>>(Wp, bp);                   // 4

    // drug branch: GAT layer 1
    k_gat1_mm<<<(NN*128 + 255)/256, 256>>>(x, W1);                 // 5
    k_att1<<<(NN*32 + 255)/256, 256>>>(att_s1, att_d1);
    k_edge_max<2><<<(ET + 255)/256, 256>>>(ei);
    k_edge_den<2><<<(ET + 255)/256, 256>>>(ei);
    k_edge_acc<2><<<(ET*32 + 255)/256, 256>>>(ei);
    k_bias_elu<1><<<(NN*128 + 255)/256, 256>>>(b1);

    // GAT layer 2
    k_gat2_mm<<<NN/64, 256, 98304>>>(W2);
    k_att2<<<(NN*32 + 255)/256, 256>>>(att_s2, att_d2);
    k_edge_max<1><<<(ET + 255)/256, 256>>>(ei);
    k_edge_den<1><<<(ET + 255)/256, 256>>>(ei);
    k_edge_acc<1><<<(ET*32 + 255)/256, 256>>>(ei);
    k_bias_elu<2><<<(NN*128 + 255)/256, 256>>>(b2);

    // pooling + drug dense
    k_pool<<<(NN*32 + 255)/256, 256>>>(batch);
    k_drug<<<(NG*256 + 255)/256, 256>>>(Wd, bd);

    // head
    k_head<<<NG, 128>>>(Wf1, bf1, Wf2, bf2, Wo, bo, out);
}

// round 4
// speedup vs baseline: 1.4001x; 1.0033x over previous
#include <cuda_runtime.h>
#include <cuda_bf16.h>

#define NN 24576
#define NE 98304
#define NG 512
#define NB 512
#define LL 1000

// ---------------- scratch (device globals; runtime alloc forbidden) ----------------
__device__ float g_h1[NN*128];
__device__ float g_as1[NN*2];
__device__ float g_ad1[NN*2];
__device__ float g_m1[NN*2];
__device__ float g_den1[NN*2];
__device__ float g_e1[(NE+NN)*2];
__device__ float g_out1[NN*128];
__device__ float g_h2[NN*128];
__device__ float g_as2[NN];
__device__ float g_ad2[NN];
__device__ float g_m2[NN];
__device__ float g_den2[NN];
__device__ float g_e2[NE+NN];
__device__ float g_out2[NN*128];
__device__ float g_sums[NG*128];
__device__ float g_cnt[NG];
__device__ float g_drug[NG*256];
__device__ float g_T[3*22*64];        // conv1 token tables (bias folded into k=1)
__device__ float g_p1[NB*LL*64];      // conv1 output, [b][l][i]
__device__ float g_pmax[NB*128];
__device__ float g_prot[NB*256];

// ---------------- helpers ----------------
__device__ __forceinline__ unsigned long long ld2(const float* p) {
    return *reinterpret_cast<const unsigned long long*>(p);
}
__device__ __forceinline__ void fma2(unsigned long long& d, unsigned long long a, unsigned long long b) {
    asm("fma.rn.f32x2 %0, %1, %2, %3;" : "=l"(d) : "l"(a), "l"(b), "l"(d));
}
__device__ __forceinline__ float2 up2(unsigned long long v) {
    float2 r; asm("mov.b64 {%0, %1}, %2;" : "=f"(r.x), "=f"(r.y) : "l"(v)); return r;
}
__device__ __forceinline__ void red_add_v4(float* addr, float4 v) {
    asm volatile("red.global.add.v4.f32 [%0], {%1, %2, %3, %4};"
                 :: "l"(addr), "f"(v.x), "f"(v.y), "f"(v.z), "f"(v.w) : "memory");
}
__device__ __forceinline__ void atomicMaxFloat(float* addr, float val) {
    if (val >= 0.f) atomicMax((int*)addr, __float_as_int(val));
    else            atomicMin((unsigned int*)addr, __float_as_uint(val));
}
__device__ __forceinline__ float warp_sum(float v) {
    #pragma unroll
    for (int off = 16; off; off >>= 1) v += __shfl_down_sync(0xffffffffu, v, off);
    return v;
}
__device__ __forceinline__ float elu1(float v) { return v > 0.f ? v : expm1f(v); }

// ---------------- conv1 token tables: T[k][t][o] = sum_i Pe[t,i] * K1[o,i,k] ----------------
__global__ void k_tab(const float* __restrict__ Pe, const float* __restrict__ K1,
                      const float* __restrict__ bk1) {
    int idx = blockIdx.x * blockDim.x + threadIdx.x;
    if (idx >= 3*22*64) return;
    int o = idx & 63, r = idx >> 6;
    int t = r % 22, k = r / 22;
    float acc = (k == 1) ? bk1[o] : 0.f;
    #pragma unroll 8
    for (int i = 0; i < 64; i++) acc += Pe[t*64 + i] * K1[(o*64 + i)*3 + k];
    g_T[idx] = acc;
}

// ---------------- conv1 apply: gather + add + elu, writes g_p1 [b][l][64] ----------------
__global__ void __launch_bounds__(256) k_conv1_apply(const int* __restrict__ seq) {
    int b = blockIdx.y;
    int lofs = threadIdx.x >> 4, lq = threadIdx.x & 15;
    int l = blockIdx.x * 16 + lofs;
    if (l >= LL) return;
    int s1 = seq[b*LL + l];
    int c = lq * 4;
    float4 v = *reinterpret_cast<const float4*>(&g_T[(22 + s1)*64 + c]);
    if (l > 0) {
        int s0 = seq[b*LL + l - 1];
        float4 a = *reinterpret_cast<const float4*>(&g_T[s0*64 + c]);
        v.x += a.x; v.y += a.y; v.z += a.z; v.w += a.w;
    }
    if (l < LL-1) {
        int s2 = seq[b*LL + l + 1];
        float4 a = *reinterpret_cast<const float4*>(&g_T[(44 + s2)*64 + c]);
        v.x += a.x; v.y += a.y; v.z += a.z; v.w += a.w;
    }
    v.x = elu1(v.x); v.y = elu1(v.y); v.z = elu1(v.z); v.w = elu1(v.w);
    *reinterpret_cast<float4*>(&g_p1[((size_t)b*LL + l)*64 + c]) = v;
}

// ---------------- init ----------------
__global__ void k_init() {
    int i = blockIdx.x * blockDim.x + threadIdx.x;
    int stride = gridDim.x * blockDim.x;
    for (int idx = i; idx < NN*128; idx += stride) { g_out1[idx] = 0.f; g_out2[idx] = 0.f; }
    for (int idx = i; idx < NN*2; idx += stride) { g_m1[idx] = -3.0e38f; g_den1[idx] = 0.f; }
    for (int idx = i; idx < NN; idx += stride) { g_m2[idx] = -3.0e38f; g_den2[idx] = 0.f; }
    for (int idx = i; idx < NG*128; idx += stride) g_sums[idx] = 0.f;
    for (int idx = i; idx < NG; idx += stride) g_cnt[idx] = 0.f;
    for (int idx = i; idx < NB*128; idx += stride) g_pmax[idx] = -3.0e38f;
}

// ---------------- conv2 + fused global max pool ----------------
// Output channels split across 2 CTAs (64 each) so smem/CTA=100KB -> 2 CTAs/SM,
// 4 warps/SMSP to hide LDS latency. Persistent over 512*16*2 work items.
__global__ void __launch_bounds__(256) k_conv2(const float* __restrict__ K2, const float* __restrict__ bk2) {
    extern __shared__ float sm[];
    float* sk = sm;              // 64 o x 322 ([o'][k*64+i])
    float* sp = sm + 64*322;     // 68 rows x 66
    int tid = threadIdx.x;
    int o_base = (blockIdx.x & 1) * 64;     // this CTA's o-half (fixed across its work items)
    for (int idx = tid; idx < 64*320; idx += 256) {
        int o = idx / 320, r = idx - o*320;
        int k = r >> 6, i = r & 63;
        sk[o*322 + k*64 + i] = K2[((o_base + o)*64 + i)*5 + k];
    }
    int o0 = 4*(tid >> 4), lgrp = tid & 15;
    float bloc[4];
    #pragma unroll
    for (int a = 0; a < 4; a++) bloc[a] = bk2[o_base + o0 + a];

    // work item = tile*2 + half; this CTA only takes items with matching half
    const int NWORK = NB*16*2;
    for (int work = blockIdx.x; work < NWORK; work += gridDim.x) {
        int tile = work >> 1;               // half == blockIdx.x & 1 == work & 1 (grid even)
        int b = tile >> 4, l0 = (tile & 15) * 64;
        __syncthreads();
        for (int idx = tid; idx < 68*64; idx += 256) {
            int row = idx >> 6, i = idx & 63;
            int lg = l0 - 2 + row;
            sp[row*66 + i] = (lg >= 0 && lg < LL) ? g_p1[((size_t)b*LL + lg)*64 + i] : 0.f;
        }
        __syncthreads();
        unsigned long long acc[4][4];
        #pragma unroll
        for (int a = 0; a < 4; a++)
            #pragma unroll
            for (int j = 0; j < 4; j++) acc[a][j] = 0ull;
        #pragma unroll 2
        for (int ib = 0; ib < 64; ib += 2) {
            #pragma unroll
            for (int k = 0; k < 5; k++) {
                unsigned long long kk[4], pp[4];
                #pragma unroll
                for (int a = 0; a < 4; a++) kk[a] = ld2(sk + (o0+a)*322 + k*64 + ib);
                #pragma unroll
                for (int j = 0; j < 4; j++) pp[j] = ld2(sp + (lgrp + 16*j + k)*66 + ib);
                #pragma unroll
                for (int a = 0; a < 4; a++)
                    #pragma unroll
                    for (int j = 0; j < 4; j++) fma2(acc[a][j], pp[j], kk[a]);
            }
        }
        float rmax[4];
        #pragma unroll
        for (int a = 0; a < 4; a++) rmax[a] = -3.0e38f;
        #pragma unroll
        for (int j = 0; j < 4; j++) {
            int l = l0 + lgrp + 16*j;
            if (l < LL) {
                #pragma unroll
                for (int a = 0; a < 4; a++) {
                    float2 f = up2(acc[a][j]);
                    rmax[a] = fmaxf(rmax[a], elu1(f.x + f.y + bloc[a]));
                }
            }
        }
        __syncthreads();   // compute reads of sp done before reuse as reduce buffer
        #pragma unroll
        for (int a = 0; a < 4; a++) sp[(o0+a)*16 + lgrp] = rmax[a];
        __syncthreads();
        if (tid < 64) {
            float m = -3.0e38f;
            #pragma unroll
            for (int q = 0; q < 16; q++) m = fmaxf(m, sp[tid*16 + q]);
            atomicMaxFloat(&g_pmax[b*128 + o_base + tid], m);
        }
    }
}

// ---------------- GAT1 GEMM: x[N,5] @ W1[5,128] ----------------
__global__ void k_gat1_mm(const float* __restrict__ x, const float* __restrict__ W1) {
    int idx = blockIdx.x * blockDim.x + threadIdx.x;
    if (idx >= NN*128) return;
    int n = idx >> 7, c = idx & 127;
    float acc = 0.f;
    #pragma unroll
    for (int f = 0; f < 5; f++) acc += x[n*5 + f] * W1[f*128 + c];
    g_h1[idx] = acc;
}

// attention scalars, 2 heads of 64
__global__ void k_att1(const float* __restrict__ att_s, const float* __restrict__ att_d) {
    int gw = (blockIdx.x * blockDim.x + threadIdx.x) >> 5;
    int lane = threadIdx.x & 31;
    if (gw >= NN) return;
    const float* hr = g_h1 + (size_t)gw * 128;
    float s0 = hr[lane]*att_s[lane] + hr[lane+32]*att_s[lane+32];
    float s1 = hr[lane+64]*att_s[lane+64] + hr[lane+96]*att_s[lane+96];
    float d0 = hr[lane]*att_d[lane] + hr[lane+32]*att_d[lane+32];
    float d1 = hr[lane+64]*att_d[lane+64] + hr[lane+96]*att_d[lane+96];
    s0 = warp_sum(s0); s1 = warp_sum(s1); d0 = warp_sum(d0); d1 = warp_sum(d1);
    if (lane == 0) {
        g_as1[gw*2] = s0; g_as1[gw*2+1] = s1;
        g_ad1[gw*2] = d0; g_ad1[gw*2+1] = d1;
    }
}

// attention scalars, 1 head of 128
__global__ void k_att2(const float* __restrict__ att_s, const float* __restrict__ att_d) {
    int gw = (blockIdx.x * blockDim.x + threadIdx.x) >> 5;
    int lane = threadIdx.x & 31;
    if (gw >= NN) return;
    const float* hr = g_h2 + (size_t)gw * 128;
    float s = 0.f, d = 0.f;
    #pragma unroll
    for (int t = 0; t < 4; t++) {
        int p = lane + 32*t;
        s += hr[p]*att_s[p];
        d += hr[p]*att_d[p];
    }
    s = warp_sum(s); d = warp_sum(d);
    if (lane == 0) { g_as2[gw] = s; g_ad2[gw] = d; }
}

// ---------------- edge passes (segment softmax + aggregation) ----------------
template<int H>
__global__ void k_edge_max(const int* __restrict__ ei) {
    int e = blockIdx.x * blockDim.x + threadIdx.x;
    const int ET = NE + NN;
    if (e >= ET) return;
    int src, dst;
    if (e < NE) { src = ei[e]; dst = ei[NE + e]; } else { src = dst = e - NE; }
    const float* as_ = (H == 2) ? g_as1 : g_as2;
    const float* ad_ = (H == 2) ? g_ad1 : g_ad2;
    float* m_ = (H == 2) ? g_m1 : g_m2;
    float* e_ = (H == 2) ? g_e1 : g_e2;
    #pragma unroll
    for (int h = 0; h < H; h++) {
        float v = as_[src*H+h] + ad_[dst*H+h];
        v = v > 0.f ? v : 0.2f * v;
        e_[e*H+h] = v;
        atomicMaxFloat(&m_[dst*H+h], v);
    }
}

template<int H>
__global__ void k_edge_den(const int* __restrict__ ei) {
    int e = blockIdx.x * blockDim.x + threadIdx.x;
    const int ET = NE + NN;
    if (e >= ET) return;
    int dst = (e < NE) ? ei[NE + e] : (e - NE);
    const float* m_ = (H == 2) ? g_m1 : g_m2;
    float* den_ = (H == 2) ? g_den1 : g_den2;
    float* e_ = (H == 2) ? g_e1 : g_e2;
    #pragma unroll
    for (int h = 0; h < H; h++) {
        float w = expf(e_[e*H+h] - m_[dst*H+h]);
        e_[e*H+h] = w;                       // cache weight for the acc pass
        atomicAdd(&den_[dst*H+h], w);
    }
}

template<int H>
__global__ void k_edge_acc(const int* __restrict__ ei) {
    int gw = (blockIdx.x * blockDim.x + threadIdx.x) >> 5;
    int lane = threadIdx.x & 31;
    const int ET = NE + NN;
    if (gw >= ET) return;
    int src, dst;
    if (gw < NE) { src = ei[gw]; dst = ei[NE + gw]; } else { src = dst = gw - NE; }
    const float* den_ = (H == 2) ? g_den1 : g_den2;
    const float* e_ = (H == 2) ? g_e1 : g_e2;
    const float* hin = (H == 2) ? g_h1 : g_h2;
    float* outp = (H == 2) ? g_out1 : g_out2;
    int h = (H == 2 && lane >= 16) ? 1 : 0;
    float alpha = e_[gw*H + h] / (den_[dst*H + h] + 1e-16f);
    float4 v = *reinterpret_cast<const float4*>(&hin[(size_t)src*128 + lane*4]);
    v.x *= alpha; v.y *= alpha; v.z *= alpha; v.w *= alpha;
    red_add_v4(&outp[(size_t)dst*128 + lane*4], v);
}

template<int WHICH>
__global__ void k_bias_elu(const float* __restrict__ b) {
    int idx = blockIdx.x * blockDim.x + threadIdx.x;
    if (idx >= NN*128) return;
    float* o = (WHICH == 1) ? g_out1 : g_out2;
    o[idx] = elu1(o[idx] + b[idx & 127]);
}

// ---------------- GAT2 GEMM: out1[N,128] @ W2[128,128] -> g_h2 ----------------
__global__ void __launch_bounds__(256) k_gat2_mm(const float* __restrict__ W2) {
    extern __shared__ float sm[];
    float* sg = sm;            // 64 x 128
    float* sw = sm + 64*128;   // 128 x 128
    int base = blockIdx.x * 64;
    int tid = threadIdx.x;
    for (int idx = tid; idx < 64*128; idx += 256) sg[idx] = g_out1[(size_t)base*128 + idx];
    for (int idx = tid; idx < 128*128; idx += 256) sw[idx] = W2[idx];
    __syncthreads();
    int r0 = (tid >> 4) << 2;
    int c0 = (tid & 15) << 3;
    float acc[4][8];
    #pragma unroll
    for (int i = 0; i < 4; i++)
        #pragma unroll
        for (int j = 0; j < 8; j++) acc[i][j] = 0.f;
    #pragma unroll 4
    for (int k = 0; k < 128; k++) {
        float a[4];
        #pragma unroll
        for (int i = 0; i < 4; i++) a[i] = sg[(r0+i)*128 + k];
        float4 b0 = *reinterpret_cast<const float4*>(&sw[k*128 + c0]);
        float4 b1 = *reinterpret_cast<const float4*>(&sw[k*128 + c0 + 4]);
        #pragma unroll
        for (int i = 0; i < 4; i++) {
            acc[i][0] += a[i]*b0.x; acc[i][1] += a[i]*b0.y;
            acc[i][2] += a[i]*b0.z; acc[i][3] += a[i]*b0.w;
            acc[i][4] += a[i]*b1.x; acc[i][5] += a[i]*b1.y;
            acc[i][6] += a[i]*b1.z; acc[i][7] += a[i]*b1.w;
        }
    }
    #pragma unroll
    for (int i = 0; i < 4; i++) {
        float4 v0 = make_float4(acc[i][0], acc[i][1], acc[i][2], acc[i][3]);
        float4 v1 = make_float4(acc[i][4], acc[i][5], acc[i][6], acc[i][7]);
        *reinterpret_cast<float4*>(&g_h2[(size_t)(base+r0+i)*128 + c0]) = v0;
        *reinterpret_cast<float4*>(&g_h2[(size_t)(base+r0+i)*128 + c0 + 4]) = v1;
    }
}

// ---------------- mean pooling + drug dense ----------------
__global__ void k_pool(const int* __restrict__ batch) {
    int gw = (blockIdx.x * blockDim.x + threadIdx.x) >> 5;
    int lane = threadIdx.x & 31;
    if (gw >= NN) return;
    int g = batch[gw];
    float4 v = *reinterpret_cast<const float4*>(&g_out2[(size_t)gw*128 + lane*4]);
    red_add_v4(&g_sums[g*128 + lane*4], v);
    if (lane == 0) atomicAdd(&g_cnt[g], 1.0f);
}

__global__ void k_drug(const float* __restrict__ Wd, const float* __restrict__ bd) {
    int idx = blockIdx.x * blockDim.x + threadIdx.x;
    if (idx >= NG*256) return;
    int g = idx >> 8, j = idx & 255;
    float invc = 1.f / fmaxf(g_cnt[g], 1.f);
    const float* srow = g_sums + g*128;
    float acc = 0.f;
    #pragma unroll 4
    for (int k = 0; k < 128; k++) acc += srow[k] * Wd[k*256 + j];
    g_drug[idx] = fmaxf(acc * invc + bd[j], 0.f);
}

__global__ void k_prot(const float* __restrict__ Wp, const float* __restrict__ bp) {
    int idx = blockIdx.x * blockDim.x + threadIdx.x;
    if (idx >= NB*256) return;
    int g = idx >> 8, j = idx & 255;
    const float* srow = g_pmax + g*128;
    float acc = 0.f;
    #pragma unroll 4
    for (int k = 0; k < 128; k++) acc += srow[k] * Wp[k*256 + j];
    g_prot[idx] = fmaxf(acc + bp[j], 0.f);
}

// ---------------- head MLP: [drug|prot] @ Wf1 -> Wf2 -> Wo ----------------
__global__ void __launch_bounds__(128) k_head(const float* __restrict__ Wf1, const float* __restrict__ bf1,
                                              const float* __restrict__ Wf2, const float* __restrict__ bf2,
                                              const float* __restrict__ Wo, const float* __restrict__ bo,
                                              float* __restrict__ out) {
    __shared__ float sh[512];
    __shared__ float s1[128];
    __shared__ float s2[64];
    int g = blockIdx.x, tid = threadIdx.x;
    for (int i = tid; i < 256; i += 128) {
        sh[i]       = g_drug[g*256 + i];
        sh[256 + i] = g_prot[g*256 + i];
    }
    __syncthreads();
    float acc = 0.f;
    #pragma unroll 8
    for (int k = 0; k < 512; k++) acc += sh[k] * Wf1[k*128 + tid];
    s1[tid] = fmaxf(acc + bf1[tid], 0.f);
    __syncthreads();
    if (tid < 64) {
        float a = 0.f;
        #pragma unroll 8
        for (int k = 0; k < 128; k++) a += s1[k] * Wf2[k*64 + tid];
        s2[tid] = fmaxf(a + bf2[tid], 0.f);
    }
    __syncthreads();
    if (tid < 32) {
        float a = s2[tid]*Wo[tid] + s2[tid+32]*Wo[tid+32];
        a = warp_sum(a);
        if (tid == 0) out[g] = a + bo[0];
    }
}

// ---------------- launch ----------------
extern "C" void kernel_launch(void* const* d_in, const int* in_sizes, int n_in,
                              void* d_out, int out_size) {
    const float* x        = (const float*)d_in[0];
    const int*   ei       = (const int*)d_in[1];
    const int*   batch    = (const int*)d_in[2];
    const int*   seq      = (const int*)d_in[3];
    const float* W1       = (const float*)d_in[4];
    const float* att_s1   = (const float*)d_in[5];
    const float* att_d1   = (const float*)d_in[6];
    const float* b1       = (const float*)d_in[7];
    const float* W2       = (const float*)d_in[8];
    const float* att_s2   = (const float*)d_in[9];
    const float* att_d2   = (const float*)d_in[10];
    const float* b2       = (const float*)d_in[11];
    const float* Wd       = (const float*)d_in[12];
    const float* bd       = (const float*)d_in[13];
    const float* Pe       = (const float*)d_in[14];
    const float* K1       = (const float*)d_in[15];
    const float* bk1      = (const float*)d_in[16];
    const float* K2       = (const float*)d_in[17];
    const float* bk2      = (const float*)d_in[18];
    const float* Wp       = (const float*)d_in[19];
    const float* bp       = (const float*)d_in[20];
    const float* Wf1      = (const float*)d_in[21];
    const float* bf1      = (const float*)d_in[22];
    const float* Wf2      = (const float*)d_in[23];
    const float* bf2      = (const float*)d_in[24];
    const float* Wo       = (const float*)d_in[25];
    const float* bo       = (const float*)d_in[26];
    float* out = (float*)d_out;

    cudaFuncSetAttribute(k_gat2_mm, cudaFuncAttributeMaxDynamicSharedMemorySize, 98304);
    cudaFuncSetAttribute(k_conv2,   cudaFuncAttributeMaxDynamicSharedMemorySize, 100384);

    const int ET = NE + NN;

    // protein branch
    k_tab<<<17, 256>>>(Pe, K1, bk1);                               // 0
    {
        dim3 grid((LL + 15)/16, NB);
        k_conv1_apply<<<grid, 256>>>(seq);                         // 1
    }
    k_init<<<2048, 256>>>();                                       // 2
    k_conv2<<<296, 256, 100384>>>(K2, bk2);                        // 3  <- profile target
    k_prot<<<(NB*256 + 255)/256, 256>>>(Wp, bp);                   // 4

    // drug branch: GAT layer 1
    k_gat1_mm<<<(NN*128 + 255)/256, 256>>>(x, W1);                 // 5
    k_att1<<<(NN*32 + 255)/256, 256>>>(att_s1, att_d1);
    k_edge_max<2><<<(ET + 255)/256, 256>>>(ei);
    k_edge_den<2><<<(ET + 255)/256, 256>>>(ei);
    k_edge_acc<2><<<(ET*32 + 255)/256, 256>>>(ei);
    k_bias_elu<1><<<(NN*128 + 255)/256, 256>>>(b1);

    // GAT layer 2
    k_gat2_mm<<<NN/64, 256, 98304>>>(W2);
    k_att2<<<(NN*32 + 255)/256, 256>>>(att_s2, att_d2);
    k_edge_max<1><<<(ET + 255)/256, 256>>>(ei);
    k_edge_den<1><<<(ET + 255)/256, 256>>>(ei);
    k_edge_acc<1><<<(ET*32 + 255)/256, 256>>>(ei);
    k_bias_elu<2><<<(NN*128 + 255)/256, 256>>>(b2);

    // pooling + drug dense
    k_pool<<<(NN*32 + 255)/256, 256>>>(batch);
    k_drug<<<(NG*256 + 255)/256, 256>>>(Wd, bd);

    // head
    k_head<<<NG, 128>>>(Wf1, bf1, Wf2, bf2, Wo, bo, out);
}

// round 6
// speedup vs baseline: 2.5114x; 1.7937x over previous
#include <cuda_runtime.h>
#include <cuda_bf16.h>
#include <cstdint>

#define NN 24576
#define NE 98304
#define NG 512
#define NB 512
#define LL 1000

// ---------------- scratch (device globals; runtime alloc forbidden) ----------------
__device__ float g_h1[NN*128];
__device__ float g_as1[NN*2];
__device__ float g_ad1[NN*2];
__device__ float g_m1[NN*2];
__device__ float g_den1[NN*2];
__device__ float g_e1[(NE+NN)*2];
__device__ float g_out1[NN*128];
__device__ float g_h2[NN*128];
__device__ float g_as2[NN];
__device__ float g_ad2[NN];
__device__ float g_m2[NN];
__device__ float g_den2[NN];
__device__ float g_e2[NE+NN];
__device__ float g_out2[NN*128];
__device__ float g_sums[NG*128];
__device__ float g_cnt[NG];
__device__ float g_drug[NG*256];
__device__ float g_T[3*22*64];        // conv1 token tables (bias folded into k=1)
__device__ float g_p1[NB*LL*64];      // conv1 output, [b][l][i]
__device__ float g_pmax[NB*128];
__device__ float g_prot[NB*256];

// ---------------- helpers ----------------
__device__ __forceinline__ void red_add_v4(float* addr, float4 v) {
    asm volatile("red.global.add.v4.f32 [%0], {%1, %2, %3, %4};"
                 :: "l"(addr), "f"(v.x), "f"(v.y), "f"(v.z), "f"(v.w) : "memory");
}
__device__ __forceinline__ void atomicMaxFloat(float* addr, float val) {
    if (val >= 0.f) atomicMax((int*)addr, __float_as_int(val));
    else            atomicMin((unsigned int*)addr, __float_as_uint(val));
}
__device__ __forceinline__ float warp_sum(float v) {
    #pragma unroll
    for (int off = 16; off; off >>= 1) v += __shfl_down_sync(0xffffffffu, v, off);
    return v;
}
__device__ __forceinline__ float elu1(float v) { return v > 0.f ? v : expm1f(v); }

__device__ __forceinline__ void mma_bf16(float* c, const uint32_t* a, const uint32_t* b) {
    asm volatile(
        "mma.sync.aligned.m16n8k16.row.col.f32.bf16.bf16.f32 "
        "{%0,%1,%2,%3}, {%4,%5,%6,%7}, {%8,%9}, {%0,%1,%2,%3};"
        : "+f"(c[0]), "+f"(c[1]), "+f"(c[2]), "+f"(c[3])
        : "r"(a[0]), "r"(a[1]), "r"(a[2]), "r"(a[3]), "r"(b[0]), "r"(b[1]));
}

// ---------------- conv2 via HMMA (mma.sync bf16), fused max pool ----------------
// GEMM view: M=128 output l, N=128 o, K=320 (5 taps x 64 ch); im2col by row overlap.
// A smem: 132 rows x 64ch, padded stride 72 elems; hi/lo bf16 terms.
// B smem: 128 o x 320 k, padded stride 328 elems; hi/lo bf16 terms.
#define C2_A_STRIDE 72
#define C2_AH 0
#define C2_AL 19584
#define C2_BH 39168
#define C2_B_STRIDE 328
#define C2_BL 123136
#define C2_SMEM 207104
#define C2_TILES (NB*8)

__global__ void __launch_bounds__(256) k_conv2_hmma(const float* __restrict__ K2,
                                                    const float* __restrict__ bk2) {
    extern __shared__ char smem[];
    uint32_t* AhW = reinterpret_cast<uint32_t*>(smem + C2_AH);   // word view (2 bf16/word)
    uint32_t* AlW = reinterpret_cast<uint32_t*>(smem + C2_AL);
    uint32_t* BhW = reinterpret_cast<uint32_t*>(smem + C2_BH);
    uint32_t* BlW = reinterpret_cast<uint32_t*>(smem + C2_BL);
    __nv_bfloat16* Bh = reinterpret_cast<__nv_bfloat16*>(smem + C2_BH);
    __nv_bfloat16* Bl = reinterpret_cast<__nv_bfloat16*>(smem + C2_BL);

    int tid = threadIdx.x, wid = tid >> 5, lane = tid & 31;
    int g = lane >> 2, q = lane & 3;
    int mw = (wid >> 2) * 64;      // warp M offset (0 or 64)
    int nw = (wid & 3) * 32;       // warp N offset

    // ---- B conversion (once per CTA) ----
    for (int idx = tid; idx < 128*320; idx += 256) {
        int n = idx / 320, k = idx - n*320;
        int t = k >> 6, i = k & 63;
        float v = K2[(n*64 + i)*5 + t];
        __nv_bfloat16 hb = __float2bfloat16_rn(v);
        __nv_bfloat16 lb = __float2bfloat16_rn(v - __bfloat162float(hb));
        Bh[n*C2_B_STRIDE + k] = hb;
        Bl[n*C2_B_STRIDE + k] = lb;
    }

    // bias per ntile col pair
    float bias[4][2];
    #pragma unroll
    for (int nt = 0; nt < 4; nt++) {
        int col = nw + nt*8 + q*2;
        bias[nt][0] = bk2[col];
        bias[nt][1] = bk2[col + 1];
    }

    for (int tile = blockIdx.x; tile < C2_TILES; tile += gridDim.x) {
        int b = tile >> 3, l0 = (tile & 7) * 125;
        __syncthreads();   // prior iter's A reads done (mma consumed pre-epilogue)

        // ---- A load + hi/lo conversion: rows 0..131 (l = l0 + row - 2) ----
        for (int idx = tid; idx < 132*32; idx += 256) {
            int row = idx >> 5, p = idx & 31;
            int l = l0 + row - 2;
            float2 v = make_float2(0.f, 0.f);
            if (l >= 0 && l < LL)
                v = *reinterpret_cast<const float2*>(&g_p1[((size_t)b*LL + l)*64 + p*2]);
            __nv_bfloat162 h2 = __floats2bfloat162_rn(v.x, v.y);
            __nv_bfloat162 l2 = __floats2bfloat162_rn(v.x - __bfloat162float(h2.x),
                                                      v.y - __bfloat162float(h2.y));
            AhW[row*(C2_A_STRIDE/2) + p] = *reinterpret_cast<uint32_t*>(&h2);
            AlW[row*(C2_A_STRIDE/2) + p] = *reinterpret_cast<uint32_t*>(&l2);
        }
        __syncthreads();

        // ---- GEMM mainloop ----
        float acc[4][4][4];
        #pragma unroll
        for (int mt = 0; mt < 4; mt++)
            #pragma unroll
            for (int nt = 0; nt < 4; nt++)
                #pragma unroll
                for (int j = 0; j < 4; j++) acc[mt][nt][j] = 0.f;

        #pragma unroll 1
        for (int ks = 0; ks < 20; ks++) {
            int t = ks >> 2;                 // tap
            int iw = (ks & 3) * 8;           // i0/2: word offset within 64-ch row
            // B fragments (all ntiles, hi+lo)
            uint32_t bh[4][2], bl[4][2];
            #pragma unroll
            for (int nt = 0; nt < 4; nt++) {
                int n = nw + nt*8 + g;
                int base = n*(C2_B_STRIDE/2) + t*32 + iw + q;
                bh[nt][0] = BhW[base];     bh[nt][1] = BhW[base + 4];
                bl[nt][0] = BlW[base];     bl[nt][1] = BlW[base + 4];
            }
            #pragma unroll
            for (int mt = 0; mt < 4; mt++) {
                int r0 = mw + mt*16 + g + t;
                int w0 = r0*(C2_A_STRIDE/2) + iw + q;
                int w8 = w0 + 8*(C2_A_STRIDE/2);
                uint32_t ah[4], al[4];
                ah[0] = AhW[w0]; ah[1] = AhW[w8]; ah[2] = AhW[w0 + 4]; ah[3] = AhW[w8 + 4];
                al[0] = AlW[w0]; al[1] = AlW[w8]; al[2] = AlW[w0 + 4]; al[3] = AlW[w8 + 4];
                #pragma unroll
                for (int nt = 0; nt < 4; nt++) {
                    mma_bf16(acc[mt][nt], ah, bh[nt]);
                    mma_bf16(acc[mt][nt], ah, bl[nt]);
                    mma_bf16(acc[mt][nt], al, bh[nt]);
                }
            }
        }

        // ---- epilogue: bias + elu + max over valid l ----
        float mx[4][2];
        #pragma unroll
        for (int nt = 0; nt < 4; nt++) { mx[nt][0] = -3.0e38f; mx[nt][1] = -3.0e38f; }
        #pragma unroll
        for (int mt = 0; mt < 4; mt++) {
            int lr = l0 + mw + mt*16 + g;
            bool v0 = lr < LL, v1 = (lr + 8) < LL;
            #pragma unroll
            for (int nt = 0; nt < 4; nt++) {
                if (v0) {
                    mx[nt][0] = fmaxf(mx[nt][0], elu1(acc[mt][nt][0] + bias[nt][0]));
                    mx[nt][1] = fmaxf(mx[nt][1], elu1(acc[mt][nt][1] + bias[nt][1]));
                }
                if (v1) {
                    mx[nt][0] = fmaxf(mx[nt][0], elu1(acc[mt][nt][2] + bias[nt][0]));
                    mx[nt][1] = fmaxf(mx[nt][1], elu1(acc[mt][nt][3] + bias[nt][1]));
                }
            }
        }
        // reduce over 8 lanes sharing the same q
        #pragma unroll
        for (int nt = 0; nt < 4; nt++) {
            #pragma unroll
            for (int j = 0; j < 2; j++) {
                float v = mx[nt][j];
                v = fmaxf(v, __shfl_xor_sync(0xffffffffu, v, 4));
                v = fmaxf(v, __shfl_xor_sync(0xffffffffu, v, 8));
                v = fmaxf(v, __shfl_xor_sync(0xffffffffu, v, 16));
                if (lane < 4)
                    atomicMaxFloat(&g_pmax[b*128 + nw + nt*8 + lane*2 + j], v);
            }
        }
    }
}

// ---------------- conv1 token tables: T[k][t][o] = sum_i Pe[t,i] * K1[o,i,k] ----------------
__global__ void k_tab(const float* __restrict__ Pe, const float* __restrict__ K1,
                      const float* __restrict__ bk1) {
    int idx = blockIdx.x * blockDim.x + threadIdx.x;
    if (idx >= 3*22*64) return;
    int o = idx & 63, r = idx >> 6;
    int t = r % 22, k = r / 22;
    float acc = (k == 1) ? bk1[o] : 0.f;
    #pragma unroll 8
    for (int i = 0; i < 64; i++) acc += Pe[t*64 + i] * K1[(o*64 + i)*3 + k];
    g_T[idx] = acc;
}

// ---------------- conv1 apply: gather + add + elu, writes g_p1 [b][l][64] ----------------
__global__ void __launch_bounds__(256) k_conv1_apply(const int* __restrict__ seq) {
    int b = blockIdx.y;
    int lofs = threadIdx.x >> 4, lq = threadIdx.x & 15;
    int l = blockIdx.x * 16 + lofs;
    if (l >= LL) return;
    int s1 = seq[b*LL + l];
    int c = lq * 4;
    float4 v = *reinterpret_cast<const float4*>(&g_T[(22 + s1)*64 + c]);
    if (l > 0) {
        int s0 = seq[b*LL + l - 1];
        float4 a = *reinterpret_cast<const float4*>(&g_T[s0*64 + c]);
        v.x += a.x; v.y += a.y; v.z += a.z; v.w += a.w;
    }
    if (l < LL-1) {
        int s2 = seq[b*LL + l + 1];
        float4 a = *reinterpret_cast<const float4*>(&g_T[(44 + s2)*64 + c]);
        v.x += a.x; v.y += a.y; v.z += a.z; v.w += a.w;
    }
    v.x = elu1(v.x); v.y = elu1(v.y); v.z = elu1(v.z); v.w = elu1(v.w);
    *reinterpret_cast<float4*>(&g_p1[((size_t)b*LL + l)*64 + c]) = v;
}

// ---------------- init ----------------
__global__ void k_init() {
    int i = blockIdx.x * blockDim.x + threadIdx.x;
    int stride = gridDim.x * blockDim.x;
    for (int idx = i; idx < NN*128; idx += stride) { g_out1[idx] = 0.f; g_out2[idx] = 0.f; }
    for (int idx = i; idx < NN*2; idx += stride) { g_m1[idx] = -3.0e38f; g_den1[idx] = 0.f; }
    for (int idx = i; idx < NN; idx += stride) { g_m2[idx] = -3.0e38f; g_den2[idx] = 0.f; }
    for (int idx = i; idx < NG*128; idx += stride) g_sums[idx] = 0.f;
    for (int idx = i; idx < NG; idx += stride) g_cnt[idx] = 0.f;
    for (int idx = i; idx < NB*128; idx += stride) g_pmax[idx] = -3.0e38f;
}

// ---------------- GAT1 GEMM: x[N,5] @ W1[5,128] ----------------
__global__ void k_gat1_mm(const float* __restrict__ x, const float* __restrict__ W1) {
    int idx = blockIdx.x * blockDim.x + threadIdx.x;
    if (idx >= NN*128) return;
    int n = idx >> 7, c = idx & 127;
    float acc = 0.f;
    #pragma unroll
    for (int f = 0; f < 5; f++) acc += x[n*5 + f] * W1[f*128 + c];
    g_h1[idx] = acc;
}

// attention scalars, 2 heads of 64
__global__ void k_att1(const float* __restrict__ att_s, const float* __restrict__ att_d) {
    int gw = (blockIdx.x * blockDim.x + threadIdx.x) >> 5;
    int lane = threadIdx.x & 31;
    if (gw >= NN) return;
    const float* hr = g_h1 + (size_t)gw * 128;
    float s0 = hr[lane]*att_s[lane] + hr[lane+32]*att_s[lane+32];
    float s1 = hr[lane+64]*att_s[lane+64] + hr[lane+96]*att_s[lane+96];
    float d0 = hr[lane]*att_d[lane] + hr[lane+32]*att_d[lane+32];
    float d1 = hr[lane+64]*att_d[lane+64] + hr[lane+96]*att_d[lane+96];
    s0 = warp_sum(s0); s1 = warp_sum(s1); d0 = warp_sum(d0); d1 = warp_sum(d1);
    if (lane == 0) {
        g_as1[gw*2] = s0; g_as1[gw*2+1] = s1;
        g_ad1[gw*2] = d0; g_ad1[gw*2+1] = d1;
    }
}

// attention scalars, 1 head of 128
__global__ void k_att2(const float* __restrict__ att_s, const float* __restrict__ att_d) {
    int gw = (blockIdx.x * blockDim.x + threadIdx.x) >> 5;
    int lane = threadIdx.x & 31;
    if (gw >= NN) return;
    const float* hr = g_h2 + (size_t)gw * 128;
    float s = 0.f, d = 0.f;
    #pragma unroll
    for (int t = 0; t < 4; t++) {
        int p = lane + 32*t;
        s += hr[p]*att_s[p];
        d += hr[p]*att_d[p];
    }
    s = warp_sum(s); d = warp_sum(d);
    if (lane == 0) { g_as2[gw] = s; g_ad2[gw] = d; }
}

// ---------------- edge passes (segment softmax + aggregation) ----------------
template<int H>
__global__ void k_edge_max(const int* __restrict__ ei) {
    int e = blockIdx.x * blockDim.x + threadIdx.x;
    const int ET = NE + NN;
    if (e >= ET) return;
    int src, dst;
    if (e < NE) { src = ei[e]; dst = ei[NE + e]; } else { src = dst = e - NE; }
    const float* as_ = (H == 2) ? g_as1 : g_as2;
    const float* ad_ = (H == 2) ? g_ad1 : g_ad2;
    float* m_ = (H == 2) ? g_m1 : g_m2;
    float* e_ = (H == 2) ? g_e1 : g_e2;
    #pragma unroll
    for (int h = 0; h < H; h++) {
        float v = as_[src*H+h] + ad_[dst*H+h];
        v = v > 0.f ? v : 0.2f * v;
        e_[e*H+h] = v;
        atomicMaxFloat(&m_[dst*H+h], v);
    }
}

template<int H>
__global__ void k_edge_den(const int* __restrict__ ei) {
    int e = blockIdx.x * blockDim.x + threadIdx.x;
    const int ET = NE + NN;
    if (e >= ET) return;
    int dst = (e < NE) ? ei[NE + e] : (e - NE);
    const float* m_ = (H == 2) ? g_m1 : g_m2;
    float* den_ = (H == 2) ? g_den1 : g_den2;
    float* e_ = (H == 2) ? g_e1 : g_e2;
    #pragma unroll
    for (int h = 0; h < H; h++) {
        float w = expf(e_[e*H+h] - m_[dst*H+h]);
        e_[e*H+h] = w;
        atomicAdd(&den_[dst*H+h], w);
    }
}

template<int H>
__global__ void k_edge_acc(const int* __restrict__ ei) {
    int gw = (blockIdx.x * blockDim.x + threadIdx.x) >> 5;
    int lane = threadIdx.x & 31;
    const int ET = NE + NN;
    if (gw >= ET) return;
    int src, dst;
    if (gw < NE) { src = ei[gw]; dst = ei[NE + gw]; } else { src = dst = gw - NE; }
    const float* den_ = (H == 2) ? g_den1 : g_den2;
    const float* e_ = (H == 2) ? g_e1 : g_e2;
    const float* hin = (H == 2) ? g_h1 : g_h2;
    float* outp = (H == 2) ? g_out1 : g_out2;
    int h = (H == 2 && lane >= 16) ? 1 : 0;
    float alpha = e_[gw*H + h] / (den_[dst*H + h] + 1e-16f);
    float4 v = *reinterpret_cast<const float4*>(&hin[(size_t)src*128 + lane*4]);
    v.x *= alpha; v.y *= alpha; v.z *= alpha; v.w *= alpha;
    red_add_v4(&outp[(size_t)dst*128 + lane*4], v);
}

template<int WHICH>
__global__ void k_bias_elu(const float* __restrict__ b) {
    int idx = blockIdx.x * blockDim.x + threadIdx.x;
    if (idx >= NN*128) return;
    float* o = (WHICH == 1) ? g_out1 : g_out2;
    o[idx] = elu1(o[idx] + b[idx & 127]);
}

// ---------------- GAT2 GEMM: out1[N,128] @ W2[128,128] -> g_h2 ----------------
__global__ void __launch_bounds__(256) k_gat2_mm(const float* __restrict__ W2) {
    extern __shared__ float sm[];
    float* sg = sm;            // 64 x 128
    float* sw = sm + 64*128;   // 128 x 128
    int base = blockIdx.x * 64;
    int tid = threadIdx.x;
    for (int idx = tid; idx < 64*128; idx += 256) sg[idx] = g_out1[(size_t)base*128 + idx];
    for (int idx = tid; idx < 128*128; idx += 256) sw[idx] = W2[idx];
    __syncthreads();
    int r0 = (tid >> 4) << 2;
    int c0 = (tid & 15) << 3;
    float acc[4][8];
    #pragma unroll
    for (int i = 0; i < 4; i++)
        #pragma unroll
        for (int j = 0; j < 8; j++) acc[i][j] = 0.f;
    #pragma unroll 4
    for (int k = 0; k < 128; k++) {
        float a[4];
        #pragma unroll
        for (int i = 0; i < 4; i++) a[i] = sg[(r0+i)*128 + k];
        float4 b0 = *reinterpret_cast<const float4*>(&sw[k*128 + c0]);
        float4 b1 = *reinterpret_cast<const float4*>(&sw[k*128 + c0 + 4]);
        #pragma unroll
        for (int i = 0; i < 4; i++) {
            acc[i][0] += a[i]*b0.x; acc[i][1] += a[i]*b0.y;
            acc[i][2] += a[i]*b0.z; acc[i][3] += a[i]*b0.w;
            acc[i][4] += a[i]*b1.x; acc[i][5] += a[i]*b1.y;
            acc[i][6] += a[i]*b1.z; acc[i][7] += a[i]*b1.w;
        }
    }
    #pragma unroll
    for (int i = 0; i < 4; i++) {
        float4 v0 = make_float4(acc[i][0], acc[i][1], acc[i][2], acc[i][3]);
        float4 v1 = make_float4(acc[i][4], acc[i][5], acc[i][6], acc[i][7]);
        *reinterpret_cast<float4*>(&g_h2[(size_t)(base+r0+i)*128 + c0]) = v0;
        *reinterpret_cast<float4*>(&g_h2[(size_t)(base+r0+i)*128 + c0 + 4]) = v1;
    }
}

// ---------------- mean pooling + drug dense ----------------
__global__ void k_pool(const int* __restrict__ batch) {
    int gw = (blockIdx.x * blockDim.x + threadIdx.x) >> 5;
    int lane = threadIdx.x & 31;
    if (gw >= NN) return;
    int g = batch[gw];
    float4 v = *reinterpret_cast<const float4*>(&g_out2[(size_t)gw*128 + lane*4]);
    red_add_v4(&g_sums[g*128 + lane*4], v);
    if (lane == 0) atomicAdd(&g_cnt[g], 1.0f);
}

__global__ void k_drug(const float* __restrict__ Wd, const float* __restrict__ bd) {
    int idx = blockIdx.x * blockDim.x + threadIdx.x;
    if (idx >= NG*256) return;
    int g = idx >> 8, j = idx & 255;
    float invc = 1.f / fmaxf(g_cnt[g], 1.f);
    const float* srow = g_sums + g*128;
    float acc = 0.f;
    #pragma unroll 4
    for (int k = 0; k < 128; k++) acc += srow[k] * Wd[k*256 + j];
    g_drug[idx] = fmaxf(acc * invc + bd[j], 0.f);
}

__global__ void k_prot(const float* __restrict__ Wp, const float* __restrict__ bp) {
    int idx = blockIdx.x * blockDim.x + threadIdx.x;
    if (idx >= NB*256) return;
    int g = idx >> 8, j = idx & 255;
    const float* srow = g_pmax + g*128;
    float acc = 0.f;
    #pragma unroll 4
    for (int k = 0; k < 128; k++) acc += srow[k] * Wp[k*256 + j];
    g_prot[idx] = fmaxf(acc + bp[j], 0.f);
}

// ---------------- head MLP ----------------
__global__ void __launch_bounds__(128) k_head(const float* __restrict__ Wf1, const float* __restrict__ bf1,
                                              const float* __restrict__ Wf2, const float* __restrict__ bf2,
                                              const float* __restrict__ Wo, const float* __restrict__ bo,
                                              float* __restrict__ out) {
    __shared__ float sh[512];
    __shared__ float s1[128];
    __shared__ float s2[64];
    int g = blockIdx.x, tid = threadIdx.x;
    for (int i = tid; i < 256; i += 128) {
        sh[i]       = g_drug[g*256 + i];
        sh[256 + i] = g_prot[g*256 + i];
    }
    __syncthreads();
    float acc = 0.f;
    #pragma unroll 8
    for (int k = 0; k < 512; k++) acc += sh[k] * Wf1[k*128 + tid];
    s1[tid] = fmaxf(acc + bf1[tid], 0.f);
    __syncthreads();
    if (tid < 64) {
        float a = 0.f;
        #pragma unroll 8
        for (int k = 0; k < 128; k++) a += s1[k] * Wf2[k*64 + tid];
        s2[tid] = fmaxf(a + bf2[tid], 0.f);
    }
    __syncthreads();
    if (tid < 32) {
        float a = s2[tid]*Wo[tid] + s2[tid+32]*Wo[tid+32];
        a = warp_sum(a);
        if (tid == 0) out[g] = a + bo[0];
    }
}

// ---------------- launch ----------------
extern "C" void kernel_launch(void* const* d_in, const int* in_sizes, int n_in,
                              void* d_out, int out_size) {
    const float* x        = (const float*)d_in[0];
    const int*   ei       = (const int*)d_in[1];
    const int*   batch    = (const int*)d_in[2];
    const int*   seq      = (const int*)d_in[3];
    const float* W1       = (const float*)d_in[4];
    const float* att_s1   = (const float*)d_in[5];
    const float* att_d1   = (const float*)d_in[6];
    const float* b1       = (const float*)d_in[7];
    const float* W2       = (const float*)d_in[8];
    const float* att_s2   = (const float*)d_in[9];
    const float* att_d2   = (const float*)d_in[10];
    const float* b2       = (const float*)d_in[11];
    const float* Wd       = (const float*)d_in[12];
    const float* bd       = (const float*)d_in[13];
    const float* Pe       = (const float*)d_in[14];
    const float* K1       = (const float*)d_in[15];
    const float* bk1      = (const float*)d_in[16];
    const float* K2       = (const float*)d_in[17];
    const float* bk2      = (const float*)d_in[18];
    const float* Wp       = (const float*)d_in[19];
    const float* bp       = (const float*)d_in[20];
    const float* Wf1      = (const float*)d_in[21];
    const float* bf1      = (const float*)d_in[22];
    const float* Wf2      = (const float*)d_in[23];
    const float* bf2      = (const float*)d_in[24];
    const float* Wo       = (const float*)d_in[25];
    const float* bo       = (const float*)d_in[26];
    float* out = (float*)d_out;

    cudaFuncSetAttribute(k_gat2_mm,    cudaFuncAttributeMaxDynamicSharedMemorySize, 98304);
    cudaFuncSetAttribute(k_conv2_hmma, cudaFuncAttributeMaxDynamicSharedMemorySize, C2_SMEM);

    const int ET = NE + NN;

    // protein branch
    k_tab<<<17, 256>>>(Pe, K1, bk1);                               // 0
    {
        dim3 grid((LL + 15)/16, NB);
        k_conv1_apply<<<grid, 256>>>(seq);                         // 1
    }
    k_init<<<2048, 256>>>();                                       // 2
    k_conv2_hmma<<<148, 256, C2_SMEM>>>(K2, bk2);                  // 3  <- profile target
    k_prot<<<(NB*256 + 255)/256, 256>>>(Wp, bp);                   // 4

    // drug branch: GAT layer 1
    k_gat1_mm<<<(NN*128 + 255)/256, 256>>>(x, W1);                 // 5
    k_att1<<<(NN*32 + 255)/256, 256>>>(att_s1, att_d1);
    k_edge_max<2><<<(ET + 255)/256, 256>>>(ei);
    k_edge_den<2><<<(ET + 255)/256, 256>>>(ei);
    k_edge_acc<2><<<(ET*32 + 255)/256, 256>>>(ei);
    k_bias_elu<1><<<(NN*128 + 255)/256, 256>>>(b1);

    // GAT layer 2
    k_gat2_mm<<<NN/64, 256, 98304>>>(W2);
    k_att2<<<(NN*32 + 255)/256, 256>>>(att_s2, att_d2);
    k_edge_max<1><<<(ET + 255)/256, 256>>>(ei);
    k_edge_den<1><<<(ET + 255)/256, 256>>>(ei);
    k_edge_acc<1><<<(ET*32 + 255)/256, 256>>>(ei);
    k_bias_elu<2><<<(NN*128 + 255)/256, 256>>>(b2);

    // pooling + drug dense
    k_pool<<<(NN*32 + 255)/256, 256>>>(batch);
    k_drug<<<(NG*256 + 255)/256, 256>>>(Wd, bd);

    // head
    k_head<<<NG, 128>>>(Wf1, bf1, Wf2, bf2, Wo, bo, out);
}